// round 16
// baseline (speedup 1.0000x reference)
#include <cuda_runtime.h>
#include <cuda_bf16.h>
#include <cstdint>
#include <math.h>

#define HID 1024
#define NHEAD 16
#define HDIM 64
#define BATCH 2
#define SEQ 2048
#define M_TOT (BATCH * SEQ)     // 4096
#define N_QKV (3 * HID)         // 3072

// ---------------------------------------------------------------------------
// Scratch: separate hi/lo matrices
// ---------------------------------------------------------------------------
__device__ __nv_bfloat16 g_qkvh[(size_t)M_TOT * N_QKV];
__device__ __nv_bfloat16 g_qkvl[(size_t)M_TOT * N_QKV];
__device__ __nv_bfloat16 g_xh[(size_t)M_TOT * HID];
__device__ __nv_bfloat16 g_xl[(size_t)M_TOT * HID];
__device__ __nv_bfloat16 g_wqh[(size_t)N_QKV * HID];
__device__ __nv_bfloat16 g_wql[(size_t)N_QKV * HID];
__device__ __nv_bfloat16 g_atth[(size_t)M_TOT * HID];
__device__ __nv_bfloat16 g_attl[(size_t)M_TOT * HID];
__device__ __nv_bfloat16 g_woh[(size_t)HID * HID];
__device__ __nv_bfloat16 g_wol[(size_t)HID * HID];

// 0.125 * log2(e): folded into Q columns of GEMM1 epilogue
#define QSCALE 0.18033688011112042f

// ---------------------------------------------------------------------------
// Helpers
// ---------------------------------------------------------------------------
__device__ __forceinline__ uint32_t smem_u32(const void* p) {
    uint32_t a;
    asm("{ .reg .u64 t; cvta.to.shared.u64 t, %1; cvt.u32.u64 %0, t; }"
        : "=r"(a) : "l"(p));
    return a;
}
__device__ __forceinline__ void cp16(uint32_t dst, const void* src) {
    asm volatile("cp.async.cg.shared.global [%0], [%1], 16;" :: "r"(dst), "l"(src));
}
__device__ __forceinline__ void cp_commit() { asm volatile("cp.async.commit_group;"); }
template <int N>
__device__ __forceinline__ void cp_wait() { asm volatile("cp.async.wait_group %0;" :: "n"(N)); }

__device__ __forceinline__ void ldm_x4(uint32_t addr, uint32_t& r0, uint32_t& r1,
                                       uint32_t& r2, uint32_t& r3) {
    asm volatile("ldmatrix.sync.aligned.m8n8.x4.shared.b16 {%0,%1,%2,%3}, [%4];"
                 : "=r"(r0), "=r"(r1), "=r"(r2), "=r"(r3) : "r"(addr));
}
__device__ __forceinline__ void ldm_x4_t(uint32_t addr, uint32_t& r0, uint32_t& r1,
                                         uint32_t& r2, uint32_t& r3) {
    asm volatile("ldmatrix.sync.aligned.m8n8.x4.trans.shared.b16 {%0,%1,%2,%3}, [%4];"
                 : "=r"(r0), "=r"(r1), "=r"(r2), "=r"(r3) : "r"(addr));
}
__device__ __forceinline__ void mma_bf16(float* c, const uint32_t* a,
                                         uint32_t b0, uint32_t b1) {
    asm volatile(
        "mma.sync.aligned.m16n8k16.row.col.f32.bf16.bf16.f32 "
        "{%0,%1,%2,%3}, {%4,%5,%6,%7}, {%8,%9}, {%0,%1,%2,%3};"
        : "+f"(c[0]), "+f"(c[1]), "+f"(c[2]), "+f"(c[3])
        : "r"(a[0]), "r"(a[1]), "r"(a[2]), "r"(a[3]), "r"(b0), "r"(b1));
}
__device__ __forceinline__ uint32_t packbf(float a, float b) {
    __nv_bfloat162 t = __floats2bfloat162_rn(a, b);
    return *(uint32_t*)&t;
}
__device__ __forceinline__ float ex2f(float x) {
    float r;
    asm("ex2.approx.f32 %0, %1;" : "=f"(r) : "f"(x));
    return r;
}

// ---------------------------------------------------------------------------
// Split fp32 -> separate bf16 hi and lo matrices
// ---------------------------------------------------------------------------
__global__ void __launch_bounds__(256) split_pair(
    const float* __restrict__ in, __nv_bfloat16* __restrict__ oh,
    __nv_bfloat16* __restrict__ ol, int total_half)
{
    for (int i = blockIdx.x * blockDim.x + threadIdx.x; i < total_half;
         i += gridDim.x * blockDim.x) {
        float2 x = *(const float2*)(in + (size_t)i * 2);
        __nv_bfloat16 h0 = __float2bfloat16(x.x);
        __nv_bfloat16 h1 = __float2bfloat16(x.y);
        __nv_bfloat162 hh, ll;
        hh.x = h0; hh.y = h1;
        ll.x = __float2bfloat16(x.x - __bfloat162float(h0));
        ll.y = __float2bfloat16(x.y - __bfloat162float(h1));
        ((__nv_bfloat162*)oh)[i] = hh;
        ((__nv_bfloat162*)ol)[i] = ll;
    }
}

// ---------------------------------------------------------------------------
// HMMA bf16x3 NT GEMM, separate hi/lo operands.
// R16: BK=32, pitch 40 (16B-aligned cp.async, conflict-free ldmatrix),
// 2-stage (81.9 KB) -> 2 CTAs/SM (16 warps/SM). 8 warps @ 64x32.
// ---------------------------------------------------------------------------
#define GBM 128
#define GBN 128
#define GBK 32
#define LDSK 40
#define STG_T (GBM * LDSK * 2)             // 10240 B per tile
#define STG_QUAD (4 * STG_T)               // 40960 B per stage
#define GEMM_SMEM (2 * STG_QUAD)           // 81920 B

struct GFrag {
    uint32_t ah[4][4], al[4][4];
    uint32_t bh[2][4], bl[2][4];
};

template <bool BF16OUT>
__global__ void __launch_bounds__(256, 2) gemm_hmma(
    const __nv_bfloat16* __restrict__ Ah, const __nv_bfloat16* __restrict__ Al,
    const __nv_bfloat16* __restrict__ Bh, const __nv_bfloat16* __restrict__ Bl,
    const float* __restrict__ bias, float* __restrict__ C,
    __nv_bfloat16* __restrict__ Ch, __nv_bfloat16* __restrict__ Cl,
    int M, int N, int K, float qsc, int qcols)
{
    extern __shared__ char gsm[];
    const uint32_t sbase = smem_u32(gsm);

    const int tid = threadIdx.x;
    const int wid = tid >> 5;
    const int lane = tid & 31;
    const int warp_m = (wid & 1) * 64;
    const int warp_n = (wid >> 1) * 32;
    const int m0 = blockIdx.y * GBM;
    const int n0 = blockIdx.x * GBN;

    const int ld_row = tid >> 2;       // 0..63
    const int ld_ch = (tid & 3) * 8;   // 0,8,16,24

    float acc[4][4][4];
#pragma unroll
    for (int i = 0; i < 4; i++)
#pragma unroll
        for (int j = 0; j < 4; j++)
#pragma unroll
            for (int q = 0; q < 4; q++) acc[i][j][q] = 0.f;

    const int NS = K / GBK;            // 32

    // stage layout: [Ah | Al | Bh | Bl], each GBM x LDSK
    auto load_stage = [&](int s, int p) {
        const int k0 = s * GBK;
        const uint32_t base = sbase + (uint32_t)p * STG_QUAD;
#pragma unroll
        for (int t = 0; t < 2; t++) {
            int row = ld_row + t * 64;
            uint32_t doff = (uint32_t)((row * LDSK + ld_ch) * 2);
            size_t ga = (size_t)(m0 + row) * K + k0 + ld_ch;
            size_t gb = (size_t)(n0 + row) * K + k0 + ld_ch;
            cp16(base + doff,              Ah + ga);
            cp16(base + STG_T + doff,      Al + ga);
            cp16(base + 2 * STG_T + doff,  Bh + gb);
            cp16(base + 3 * STG_T + doff,  Bl + gb);
        }
    };

    const int a_row = warp_m + (lane & 15);
    const int b_row = warp_n + (lane & 15);
    const int k_half = (lane >> 4) * 8;

    auto load_frags = [&](int p, int kk, GFrag& f) {
        const uint32_t base = sbase + (uint32_t)p * STG_QUAD;
        const int kc = kk * 16 + k_half;
#pragma unroll
        for (int i = 0; i < 4; i++) {
            uint32_t off = (uint32_t)(((a_row + i * 16) * LDSK + kc) * 2);
            ldm_x4(base + off,         f.ah[i][0], f.ah[i][1], f.ah[i][2], f.ah[i][3]);
            ldm_x4(base + STG_T + off, f.al[i][0], f.al[i][1], f.al[i][2], f.al[i][3]);
        }
#pragma unroll
        for (int jp = 0; jp < 2; jp++) {
            uint32_t off = (uint32_t)(((b_row + jp * 16) * LDSK + kc) * 2);
            ldm_x4(base + 2 * STG_T + off, f.bh[jp][0], f.bh[jp][1], f.bh[jp][2], f.bh[jp][3]);
            ldm_x4(base + 3 * STG_T + off, f.bl[jp][0], f.bl[jp][1], f.bl[jp][2], f.bl[jp][3]);
        }
    };

    auto mma_all = [&](GFrag& f) {
#pragma unroll
        for (int i = 0; i < 4; i++)
#pragma unroll
            for (int jp = 0; jp < 2; jp++) {
                mma_bf16(acc[i][2 * jp],     f.ah[i], f.bh[jp][0], f.bh[jp][2]);
                mma_bf16(acc[i][2 * jp + 1], f.ah[i], f.bh[jp][1], f.bh[jp][3]);
            }
#pragma unroll
        for (int i = 0; i < 4; i++)
#pragma unroll
            for (int jp = 0; jp < 2; jp++) {
                mma_bf16(acc[i][2 * jp],     f.ah[i], f.bl[jp][0], f.bl[jp][2]);
                mma_bf16(acc[i][2 * jp + 1], f.ah[i], f.bl[jp][1], f.bl[jp][3]);
            }
#pragma unroll
        for (int i = 0; i < 4; i++)
#pragma unroll
            for (int jp = 0; jp < 2; jp++) {
                mma_bf16(acc[i][2 * jp],     f.al[i], f.bh[jp][0], f.bh[jp][2]);
                mma_bf16(acc[i][2 * jp + 1], f.al[i], f.bh[jp][1], f.bh[jp][3]);
            }
    };

    load_stage(0, 0);
    cp_commit();

    GFrag f;
    for (int s = 0; s < NS; s++) {
        const int p = s & 1;
        cp_wait<0>();
        __syncthreads();
        if (s + 1 < NS) load_stage(s + 1, p ^ 1);
        cp_commit();

        load_frags(p, 0, f); mma_all(f);
        load_frags(p, 1, f); mma_all(f);
    }

    const int row_g = lane >> 2;
    const int col_g = (lane & 3) * 2;
#pragma unroll
    for (int i = 0; i < 4; i++) {
#pragma unroll
        for (int j = 0; j < 4; j++) {
            int row = m0 + warp_m + i * 16 + row_g;
            int col = n0 + warp_n + j * 8 + col_g;
            float b0 = bias[col], b1 = bias[col + 1];
            float sc = (col < qcols) ? qsc : 1.0f;
            float v00 = (acc[i][j][0] + b0) * sc, v01 = (acc[i][j][1] + b1) * sc;
            float v10 = (acc[i][j][2] + b0) * sc, v11 = (acc[i][j][3] + b1) * sc;
            if (BF16OUT) {
                __nv_bfloat162 h0 = __floats2bfloat162_rn(v00, v01);
                __nv_bfloat162 h1 = __floats2bfloat162_rn(v10, v11);
                __nv_bfloat162 l0 = __floats2bfloat162_rn(
                    v00 - __bfloat162float(h0.x), v01 - __bfloat162float(h0.y));
                __nv_bfloat162 l1 = __floats2bfloat162_rn(
                    v10 - __bfloat162float(h1.x), v11 - __bfloat162float(h1.y));
                *(__nv_bfloat162*)(Ch + (size_t)row * N + col) = h0;
                *(__nv_bfloat162*)(Ch + (size_t)(row + 8) * N + col) = h1;
                *(__nv_bfloat162*)(Cl + (size_t)row * N + col) = l0;
                *(__nv_bfloat162*)(Cl + (size_t)(row + 8) * N + col) = l1;
            } else {
                *(float2*)(C + (size_t)row * N + col) = make_float2(v00, v01);
                *(float2*)(C + (size_t)(row + 8) * N + col) = make_float2(v10, v11);
            }
        }
    }
}

// ---------------------------------------------------------------------------
// Tensor-core flash attention (unchanged R14): 64 q-rows, 128 threads,
// bf16x3 split, ex2 softmax (scale folded into Q), hi/lo output.
// ---------------------------------------------------------------------------
#define APITCH 72
#define ATILE (64 * APITCH)
#define ATT_SMEM ((2 + 8) * ATILE * 2)      // 92160 B

__global__ void __launch_bounds__(128) attn_tc(
    const __nv_bfloat16* __restrict__ qh, const __nv_bfloat16* __restrict__ ql,
    __nv_bfloat16* __restrict__ atth, __nv_bfloat16* __restrict__ attl)
{
    extern __shared__ __nv_bfloat16 sm[];
    __nv_bfloat16* Qh = sm;
    __nv_bfloat16* Ql = Qh + ATILE;
    __nv_bfloat16* KV = Ql + ATILE;

    const int tid = threadIdx.x;
    const int wid = tid >> 5;
    const int lane = tid & 31;
    const int bh = blockIdx.y;
    const int b = bh >> 4, h = bh & 15;
    const int q0 = blockIdx.x * 64;
    const size_t tokbase = (size_t)b * SEQ;

    const uint32_t sQh = smem_u32(Qh), sQl = smem_u32(Ql);
    const uint32_t sKV = smem_u32(KV);

    {
        const size_t qoff = (tokbase + q0) * N_QKV + h * HDIM;
#pragma unroll
        for (int t = 0; t < 4; t++) {
            int idx = tid + t * 128;
            int row = idx >> 3;
            int ch = (idx & 7) * 8;
            *(uint4*)(Qh + row * APITCH + ch) = *(const uint4*)(qh + qoff + (size_t)row * N_QKV + ch);
            *(uint4*)(Ql + row * APITCH + ch) = *(const uint4*)(ql + qoff + (size_t)row * N_QKV + ch);
        }
    }

    auto load_kv = [&](int kt, int p) {
        const size_t koff = (tokbase + kt * 64) * N_QKV + HID + h * HDIM;
        const size_t voff = koff + HID;
        const uint32_t base = sKV + (uint32_t)p * (4 * ATILE * 2);
#pragma unroll
        for (int t = 0; t < 4; t++) {
            int idx = tid + t * 128;
            int row = idx >> 3;
            int ch = (idx & 7) * 8;
            size_t g = (size_t)row * N_QKV + ch;
            uint32_t doff = (uint32_t)((row * APITCH + ch) * 2);
            cp16(base + doff,                 qh + koff + g);
            cp16(base + ATILE * 2 + doff,     ql + koff + g);
            cp16(base + 2 * ATILE * 2 + doff, qh + voff + g);
            cp16(base + 3 * ATILE * 2 + doff, ql + voff + g);
        }
    };

    load_kv(0, 0);
    cp_commit();
    __syncthreads();

    const int lrow = lane & 15;
    const int lkh = (lane >> 4) * 8;
    const int vkey = (lane >> 4) * 8 + (lane & 7);
    const int vd = ((lane >> 3) & 1) * 8;

    uint32_t qfh[4][4], qfl[4][4];
#pragma unroll
    for (int kk = 0; kk < 4; kk++) {
        const uint32_t qoff2 = (uint32_t)(((wid * 16 + lrow) * APITCH + kk * 16 + lkh) * 2);
        ldm_x4(sQh + qoff2, qfh[kk][0], qfh[kk][1], qfh[kk][2], qfh[kk][3]);
        ldm_x4(sQl + qoff2, qfl[kk][0], qfl[kk][1], qfl[kk][2], qfl[kk][3]);
    }

    float l0 = 0.f, l1 = 0.f;
    float o[8][4];
#pragma unroll
    for (int t = 0; t < 8; t++)
#pragma unroll
        for (int q = 0; q < 4; q++) o[t][q] = 0.f;

    const int NK = SEQ / 64;
    for (int kt = 0; kt < NK; kt++) {
        const int p = kt & 1;
        cp_wait<0>();
        __syncthreads();
        if (kt + 1 < NK) load_kv(kt + 1, p ^ 1);
        cp_commit();

        const uint32_t base = sKV + (uint32_t)p * (4 * ATILE * 2);
        const uint32_t sKh = base;
        const uint32_t sKl = base + ATILE * 2;
        const uint32_t sVh = base + 2 * ATILE * 2;
        const uint32_t sVl = base + 3 * ATILE * 2;

        auto load_kfrags = [&](int kk, uint32_t (&kh)[4][4], uint32_t (&kl)[4][4]) {
#pragma unroll
            for (int jp = 0; jp < 4; jp++) {
                const uint32_t koff2 = (uint32_t)(((jp * 16 + lrow) * APITCH + kk * 16 + lkh) * 2);
                ldm_x4(sKh + koff2, kh[jp][0], kh[jp][1], kh[jp][2], kh[jp][3]);
                ldm_x4(sKl + koff2, kl[jp][0], kl[jp][1], kl[jp][2], kl[jp][3]);
            }
        };
        auto load_vfrags = [&](int kk, uint32_t (&vh)[4][4], uint32_t (&vl)[4][4]) {
#pragma unroll
            for (int dt = 0; dt < 4; dt++) {
                const uint32_t voff2 = (uint32_t)(((kk * 16 + vkey) * APITCH + dt * 16 + vd) * 2);
                ldm_x4_t(sVh + voff2, vh[dt][0], vh[dt][1], vh[dt][2], vh[dt][3]);
                ldm_x4_t(sVl + voff2, vl[dt][0], vl[dt][1], vl[dt][2], vl[dt][3]);
            }
        };

        float sf[8][4];
#pragma unroll
        for (int t = 0; t < 8; t++)
#pragma unroll
            for (int q = 0; q < 4; q++) sf[t][q] = 0.f;

        auto s_mma = [&](int kk, uint32_t (&kh)[4][4], uint32_t (&kl)[4][4]) {
#pragma unroll
            for (int jp = 0; jp < 4; jp++) {
                mma_bf16(sf[2 * jp],     qfh[kk], kh[jp][0], kh[jp][2]);
                mma_bf16(sf[2 * jp + 1], qfh[kk], kh[jp][1], kh[jp][3]);
            }
#pragma unroll
            for (int jp = 0; jp < 4; jp++) {
                mma_bf16(sf[2 * jp],     qfh[kk], kl[jp][0], kl[jp][2]);
                mma_bf16(sf[2 * jp + 1], qfh[kk], kl[jp][1], kl[jp][3]);
            }
#pragma unroll
            for (int jp = 0; jp < 4; jp++) {
                mma_bf16(sf[2 * jp],     qfl[kk], kh[jp][0], kh[jp][2]);
                mma_bf16(sf[2 * jp + 1], qfl[kk], kh[jp][1], kh[jp][3]);
            }
        };

        {
            uint32_t khA[4][4], klA[4][4], khB[4][4], klB[4][4];
            load_kfrags(0, khA, klA);
            load_kfrags(1, khB, klB); s_mma(0, khA, klA);
            load_kfrags(2, khA, klA); s_mma(1, khB, klB);
            load_kfrags(3, khB, klB); s_mma(2, khA, klA);
            s_mma(3, khB, klB);
        }

        uint32_t vhA[4][4], vlA[4][4], vhB[4][4], vlB[4][4];
        load_vfrags(0, vhA, vlA);

#pragma unroll
        for (int t = 0; t < 8; t++) {
            sf[t][0] = ex2f(sf[t][0]);
            sf[t][1] = ex2f(sf[t][1]);
            sf[t][2] = ex2f(sf[t][2]);
            sf[t][3] = ex2f(sf[t][3]);
            l0 += sf[t][0] + sf[t][1];
            l1 += sf[t][2] + sf[t][3];
        }

        uint32_t ph[4][4], pl[4][4];
#pragma unroll
        for (int kk = 0; kk < 4; kk++) {
            float* c0 = sf[2 * kk];
            float* c1 = sf[2 * kk + 1];
            ph[kk][0] = packbf(c0[0], c0[1]);
            ph[kk][1] = packbf(c0[2], c0[3]);
            ph[kk][2] = packbf(c1[0], c1[1]);
            ph[kk][3] = packbf(c1[2], c1[3]);
            __nv_bfloat162* hp;
            hp = (__nv_bfloat162*)&ph[kk][0];
            pl[kk][0] = packbf(c0[0] - __bfloat162float(hp->x), c0[1] - __bfloat162float(hp->y));
            hp = (__nv_bfloat162*)&ph[kk][1];
            pl[kk][1] = packbf(c0[2] - __bfloat162float(hp->x), c0[3] - __bfloat162float(hp->y));
            hp = (__nv_bfloat162*)&ph[kk][2];
            pl[kk][2] = packbf(c1[0] - __bfloat162float(hp->x), c1[1] - __bfloat162float(hp->y));
            hp = (__nv_bfloat162*)&ph[kk][3];
            pl[kk][3] = packbf(c1[2] - __bfloat162float(hp->x), c1[3] - __bfloat162float(hp->y));
        }

        auto pv_mma = [&](int kk, uint32_t (&vh)[4][4], uint32_t (&vl)[4][4]) {
#pragma unroll
            for (int dt = 0; dt < 4; dt++) {
                mma_bf16(o[2 * dt],     ph[kk], vh[dt][0], vh[dt][2]);
                mma_bf16(o[2 * dt + 1], ph[kk], vh[dt][1], vh[dt][3]);
            }
#pragma unroll
            for (int dt = 0; dt < 4; dt++) {
                mma_bf16(o[2 * dt],     ph[kk], vl[dt][0], vl[dt][2]);
                mma_bf16(o[2 * dt + 1], ph[kk], vl[dt][1], vl[dt][3]);
            }
#pragma unroll
            for (int dt = 0; dt < 4; dt++) {
                mma_bf16(o[2 * dt],     pl[kk], vh[dt][0], vh[dt][2]);
                mma_bf16(o[2 * dt + 1], pl[kk], vh[dt][1], vh[dt][3]);
            }
        };

        load_vfrags(1, vhB, vlB); pv_mma(0, vhA, vlA);
        load_vfrags(2, vhA, vlA); pv_mma(1, vhB, vlB);
        load_vfrags(3, vhB, vlB); pv_mma(2, vhA, vlA);
        pv_mma(3, vhB, vlB);
    }

    l0 += __shfl_xor_sync(0xffffffffu, l0, 1);
    l0 += __shfl_xor_sync(0xffffffffu, l0, 2);
    l1 += __shfl_xor_sync(0xffffffffu, l1, 1);
    l1 += __shfl_xor_sync(0xffffffffu, l1, 2);

    const float inv0 = 1.f / l0, inv1 = 1.f / l1;
    const int gr0 = q0 + wid * 16 + (lane >> 2);
    const int gr1 = gr0 + 8;
    const size_t r0base = (tokbase + gr0) * (size_t)HID;
    const size_t r1base = (tokbase + gr1) * (size_t)HID;
#pragma unroll
    for (int t = 0; t < 8; t++) {
        int col = h * HDIM + t * 8 + (lane & 3) * 2;
        float v00 = o[t][0] * inv0, v01 = o[t][1] * inv0;
        float v10 = o[t][2] * inv1, v11 = o[t][3] * inv1;
        __nv_bfloat162 h0 = __floats2bfloat162_rn(v00, v01);
        __nv_bfloat162 h1 = __floats2bfloat162_rn(v10, v11);
        __nv_bfloat162 lo0 = __floats2bfloat162_rn(v00 - __bfloat162float(h0.x),
                                                   v01 - __bfloat162float(h0.y));
        __nv_bfloat162 lo1 = __floats2bfloat162_rn(v10 - __bfloat162float(h1.x),
                                                   v11 - __bfloat162float(h1.y));
        *(__nv_bfloat162*)(atth + r0base + col) = h0;
        *(__nv_bfloat162*)(attl + r0base + col) = lo0;
        *(__nv_bfloat162*)(atth + r1base + col) = h1;
        *(__nv_bfloat162*)(attl + r1base + col) = lo1;
    }
}

// ---------------------------------------------------------------------------
// Launch
// ---------------------------------------------------------------------------
extern "C" void kernel_launch(void* const* d_in, const int* in_sizes, int n_in,
                              void* d_out, int out_size)
{
    const float *x = nullptr, *w_qkv = nullptr, *b_qkv = nullptr,
                *w_out = nullptr, *b_out = nullptr;
    for (int i = 0; i < n_in; i++) {
        const float* p = (const float*)d_in[i];
        switch (in_sizes[i]) {
            case M_TOT * HID: x = p; break;
            case N_QKV * HID: w_qkv = p; break;
            case N_QKV:       b_qkv = p; break;
            case HID * HID:   w_out = p; break;
            case HID:         b_out = p; break;
        }
    }
    float* out = (float*)d_out;

    __nv_bfloat16 *qkvh, *qkvl, *xh, *xl, *wqh, *wql, *atth, *attl, *woh, *wol;
    cudaGetSymbolAddress((void**)&qkvh, g_qkvh);
    cudaGetSymbolAddress((void**)&qkvl, g_qkvl);
    cudaGetSymbolAddress((void**)&xh, g_xh);
    cudaGetSymbolAddress((void**)&xl, g_xl);
    cudaGetSymbolAddress((void**)&wqh, g_wqh);
    cudaGetSymbolAddress((void**)&wql, g_wql);
    cudaGetSymbolAddress((void**)&atth, g_atth);
    cudaGetSymbolAddress((void**)&attl, g_attl);
    cudaGetSymbolAddress((void**)&woh, g_woh);
    cudaGetSymbolAddress((void**)&wol, g_wol);

    cudaFuncSetAttribute(attn_tc,
                         cudaFuncAttributeMaxDynamicSharedMemorySize, ATT_SMEM);
    cudaFuncSetAttribute(gemm_hmma<true>,
                         cudaFuncAttributeMaxDynamicSharedMemorySize, GEMM_SMEM);
    cudaFuncSetAttribute(gemm_hmma<false>,
                         cudaFuncAttributeMaxDynamicSharedMemorySize, GEMM_SMEM);

    // Splits (hi/lo pairs)
    split_pair<<<512, 256>>>(x,     xh,  xl,  M_TOT * HID / 2);
    split_pair<<<512, 256>>>(w_qkv, wqh, wql, N_QKV * HID / 2);
    split_pair<<<256, 256>>>(w_out, woh, wol, HID * HID / 2);

    // GEMM1: qkv = x @ w_qkv^T + b_qkv; Q cols scaled by 0.125*log2e
    gemm_hmma<true><<<dim3(N_QKV / GBN, M_TOT / GBM), dim3(256), GEMM_SMEM>>>(
        xh, xl, wqh, wql, b_qkv, nullptr, qkvh, qkvl, M_TOT, N_QKV, HID,
        QSCALE, HID);

    // Attention
    attn_tc<<<dim3(SEQ / 64, BATCH * NHEAD), dim3(128), ATT_SMEM>>>(
        qkvh, qkvl, atth, attl);

    // GEMM2: out = att @ w_out^T + b_out (no scale)
    gemm_hmma<false><<<dim3(HID / GBN, M_TOT / GBM), dim3(256), GEMM_SMEM>>>(
        atth, attl, woh, wol, b_out, out, nullptr, nullptr, M_TOT, HID, HID,
        1.0f, 0);
}

// round 17
// speedup vs baseline: 1.1878x; 1.1878x over previous
#include <cuda_runtime.h>
#include <cuda_bf16.h>
#include <cstdint>
#include <math.h>

#define HID 1024
#define NHEAD 16
#define HDIM 64
#define BATCH 2
#define SEQ 2048
#define M_TOT (BATCH * SEQ)     // 4096
#define N_QKV (3 * HID)         // 3072

// ---------------------------------------------------------------------------
// Scratch: separate hi/lo matrices
// ---------------------------------------------------------------------------
__device__ __nv_bfloat16 g_qkvh[(size_t)M_TOT * N_QKV];
__device__ __nv_bfloat16 g_qkvl[(size_t)M_TOT * N_QKV];
__device__ __nv_bfloat16 g_xh[(size_t)M_TOT * HID];
__device__ __nv_bfloat16 g_xl[(size_t)M_TOT * HID];
__device__ __nv_bfloat16 g_wqh[(size_t)N_QKV * HID];
__device__ __nv_bfloat16 g_wql[(size_t)N_QKV * HID];
__device__ __nv_bfloat16 g_atth[(size_t)M_TOT * HID];
__device__ __nv_bfloat16 g_attl[(size_t)M_TOT * HID];
__device__ __nv_bfloat16 g_woh[(size_t)HID * HID];
__device__ __nv_bfloat16 g_wol[(size_t)HID * HID];

// 0.125 * log2(e): folded into Q columns of GEMM1 epilogue
#define QSCALE 0.18033688011112042f

// ---------------------------------------------------------------------------
// Helpers
// ---------------------------------------------------------------------------
__device__ __forceinline__ uint32_t smem_u32(const void* p) {
    uint32_t a;
    asm("{ .reg .u64 t; cvta.to.shared.u64 t, %1; cvt.u32.u64 %0, t; }"
        : "=r"(a) : "l"(p));
    return a;
}
__device__ __forceinline__ void cp16(uint32_t dst, const void* src) {
    asm volatile("cp.async.cg.shared.global [%0], [%1], 16;" :: "r"(dst), "l"(src));
}
__device__ __forceinline__ void cp_commit() { asm volatile("cp.async.commit_group;"); }
template <int N>
__device__ __forceinline__ void cp_wait() { asm volatile("cp.async.wait_group %0;" :: "n"(N)); }

__device__ __forceinline__ void ldm_x4(uint32_t addr, uint32_t& r0, uint32_t& r1,
                                       uint32_t& r2, uint32_t& r3) {
    asm volatile("ldmatrix.sync.aligned.m8n8.x4.shared.b16 {%0,%1,%2,%3}, [%4];"
                 : "=r"(r0), "=r"(r1), "=r"(r2), "=r"(r3) : "r"(addr));
}
__device__ __forceinline__ void ldm_x4_t(uint32_t addr, uint32_t& r0, uint32_t& r1,
                                         uint32_t& r2, uint32_t& r3) {
    asm volatile("ldmatrix.sync.aligned.m8n8.x4.trans.shared.b16 {%0,%1,%2,%3}, [%4];"
                 : "=r"(r0), "=r"(r1), "=r"(r2), "=r"(r3) : "r"(addr));
}
__device__ __forceinline__ void mma_bf16(float* c, const uint32_t* a,
                                         uint32_t b0, uint32_t b1) {
    asm volatile(
        "mma.sync.aligned.m16n8k16.row.col.f32.bf16.bf16.f32 "
        "{%0,%1,%2,%3}, {%4,%5,%6,%7}, {%8,%9}, {%0,%1,%2,%3};"
        : "+f"(c[0]), "+f"(c[1]), "+f"(c[2]), "+f"(c[3])
        : "r"(a[0]), "r"(a[1]), "r"(a[2]), "r"(a[3]), "r"(b0), "r"(b1));
}
__device__ __forceinline__ uint32_t packbf(float a, float b) {
    __nv_bfloat162 t = __floats2bfloat162_rn(a, b);
    return *(uint32_t*)&t;
}
__device__ __forceinline__ float ex2f(float x) {
    float r;
    asm("ex2.approx.f32 %0, %1;" : "=f"(r) : "f"(x));
    return r;
}

// ---------------------------------------------------------------------------
// Fused split: all three fp32 -> bf16 hi/lo conversions in one launch.
// ---------------------------------------------------------------------------
#define T0 (M_TOT * HID / 2)        // x:      2,097,152 float2
#define T1 (N_QKV * HID / 2)        // w_qkv:  1,572,864
#define T2 (HID * HID / 2)          // w_out:    524,288
#define TSUM (T0 + T1 + T2)

__device__ __forceinline__ void split_one(
    const float* __restrict__ in, __nv_bfloat16* __restrict__ oh,
    __nv_bfloat16* __restrict__ ol, int i)
{
    float2 x = *(const float2*)(in + (size_t)i * 2);
    __nv_bfloat16 h0 = __float2bfloat16(x.x);
    __nv_bfloat16 h1 = __float2bfloat16(x.y);
    __nv_bfloat162 hh, ll;
    hh.x = h0; hh.y = h1;
    ll.x = __float2bfloat16(x.x - __bfloat162float(h0));
    ll.y = __float2bfloat16(x.y - __bfloat162float(h1));
    ((__nv_bfloat162*)oh)[i] = hh;
    ((__nv_bfloat162*)ol)[i] = ll;
}

__global__ void __launch_bounds__(256) split_all(
    const float* __restrict__ x,  __nv_bfloat16* __restrict__ xh,  __nv_bfloat16* __restrict__ xl,
    const float* __restrict__ wq, __nv_bfloat16* __restrict__ wqh, __nv_bfloat16* __restrict__ wql,
    const float* __restrict__ wo, __nv_bfloat16* __restrict__ woh, __nv_bfloat16* __restrict__ wol)
{
    for (int i = blockIdx.x * blockDim.x + threadIdx.x; i < TSUM;
         i += gridDim.x * blockDim.x) {
        if (i < T0)            split_one(x,  xh,  xl,  i);
        else if (i < T0 + T1)  split_one(wq, wqh, wql, i - T0);
        else                   split_one(wo, woh, wol, i - T0 - T1);
    }
}

// ---------------------------------------------------------------------------
// HMMA bf16x3 NT GEMM (R14 config, proven 216us): separate hi/lo operands,
// 8 warps @ 64x32, BK=64, 3-stage cp.async, frag ping-pong. 12 LDSM / 48 MMA.
// ---------------------------------------------------------------------------
#define GBM 128
#define GBN 128
#define GBK 64
#define LDSK 72
#define GSTAGES 3
#define STG_T (GBM * LDSK * 2)             // 18432 B per tile
#define STG_QUAD (4 * STG_T)               // 73728 B per stage
#define GEMM_SMEM (GSTAGES * STG_QUAD)     // 221184 B

struct GFrag {
    uint32_t ah[4][4], al[4][4];
    uint32_t bh[2][4], bl[2][4];
};

template <bool BF16OUT>
__global__ void __launch_bounds__(256) gemm_hmma(
    const __nv_bfloat16* __restrict__ Ah, const __nv_bfloat16* __restrict__ Al,
    const __nv_bfloat16* __restrict__ Bh, const __nv_bfloat16* __restrict__ Bl,
    const float* __restrict__ bias, float* __restrict__ C,
    __nv_bfloat16* __restrict__ Ch, __nv_bfloat16* __restrict__ Cl,
    int M, int N, int K, float qsc, int qcols)
{
    extern __shared__ char gsm[];
    const uint32_t sbase = smem_u32(gsm);

    const int tid = threadIdx.x;
    const int wid = tid >> 5;
    const int lane = tid & 31;
    const int warp_m = (wid & 1) * 64;
    const int warp_n = (wid >> 1) * 32;
    const int m0 = blockIdx.y * GBM;
    const int n0 = blockIdx.x * GBN;

    const int ld_row = tid >> 3;       // 0..31
    const int ld_ch = (tid & 7) * 8;   // 0..56

    float acc[4][4][4];
#pragma unroll
    for (int i = 0; i < 4; i++)
#pragma unroll
        for (int j = 0; j < 4; j++)
#pragma unroll
            for (int q = 0; q < 4; q++) acc[i][j][q] = 0.f;

    const int NS = K / GBK;            // 16

    auto load_stage = [&](int s, int p) {
        const int k0 = s * GBK;
        const uint32_t base = sbase + (uint32_t)p * STG_QUAD;
#pragma unroll
        for (int t = 0; t < 4; t++) {
            int row = ld_row + t * 32;
            uint32_t doff = (uint32_t)((row * LDSK + ld_ch) * 2);
            size_t ga = (size_t)(m0 + row) * K + k0 + ld_ch;
            size_t gb = (size_t)(n0 + row) * K + k0 + ld_ch;
            cp16(base + doff,              Ah + ga);
            cp16(base + STG_T + doff,      Al + ga);
            cp16(base + 2 * STG_T + doff,  Bh + gb);
            cp16(base + 3 * STG_T + doff,  Bl + gb);
        }
    };

    const int a_row = warp_m + (lane & 15);
    const int b_row = warp_n + (lane & 15);
    const int k_half = (lane >> 4) * 8;

    auto load_frags = [&](int p, int kk, GFrag& f) {
        const uint32_t base = sbase + (uint32_t)p * STG_QUAD;
        const int kc = kk * 16 + k_half;
#pragma unroll
        for (int i = 0; i < 4; i++) {
            uint32_t off = (uint32_t)(((a_row + i * 16) * LDSK + kc) * 2);
            ldm_x4(base + off,         f.ah[i][0], f.ah[i][1], f.ah[i][2], f.ah[i][3]);
            ldm_x4(base + STG_T + off, f.al[i][0], f.al[i][1], f.al[i][2], f.al[i][3]);
        }
#pragma unroll
        for (int jp = 0; jp < 2; jp++) {
            uint32_t off = (uint32_t)(((b_row + jp * 16) * LDSK + kc) * 2);
            ldm_x4(base + 2 * STG_T + off, f.bh[jp][0], f.bh[jp][1], f.bh[jp][2], f.bh[jp][3]);
            ldm_x4(base + 3 * STG_T + off, f.bl[jp][0], f.bl[jp][1], f.bl[jp][2], f.bl[jp][3]);
        }
    };

    auto mma_all = [&](GFrag& f) {
#pragma unroll
        for (int i = 0; i < 4; i++)
#pragma unroll
            for (int jp = 0; jp < 2; jp++) {
                mma_bf16(acc[i][2 * jp],     f.ah[i], f.bh[jp][0], f.bh[jp][2]);
                mma_bf16(acc[i][2 * jp + 1], f.ah[i], f.bh[jp][1], f.bh[jp][3]);
            }
#pragma unroll
        for (int i = 0; i < 4; i++)
#pragma unroll
            for (int jp = 0; jp < 2; jp++) {
                mma_bf16(acc[i][2 * jp],     f.ah[i], f.bl[jp][0], f.bl[jp][2]);
                mma_bf16(acc[i][2 * jp + 1], f.ah[i], f.bl[jp][1], f.bl[jp][3]);
            }
#pragma unroll
        for (int i = 0; i < 4; i++)
#pragma unroll
            for (int jp = 0; jp < 2; jp++) {
                mma_bf16(acc[i][2 * jp],     f.al[i], f.bh[jp][0], f.bh[jp][2]);
                mma_bf16(acc[i][2 * jp + 1], f.al[i], f.bh[jp][1], f.bh[jp][3]);
            }
    };

    // Prologue: 2 stages in flight
    load_stage(0, 0); cp_commit();
    load_stage(1, 1); cp_commit();
    cp_wait<1>();
    __syncthreads();

    GFrag fA, fB;
    load_frags(0, 0, fA);

    int p = 0, pn = 2;
    for (int s = 0; s < NS; s++) {
        { int ns = s + 2; if (ns < NS) load_stage(ns, pn); cp_commit(); }

        load_frags(p, 1, fB); mma_all(fA);
        load_frags(p, 2, fA); mma_all(fB);
        load_frags(p, 3, fB); mma_all(fA);
        mma_all(fB);

        cp_wait<1>();
        __syncthreads();
        p  = (p == 2)  ? 0 : p + 1;
        pn = (pn == 2) ? 0 : pn + 1;
        if (s + 1 < NS) load_frags(p, 0, fA);
    }

    const int row_g = lane >> 2;
    const int col_g = (lane & 3) * 2;
#pragma unroll
    for (int i = 0; i < 4; i++) {
#pragma unroll
        for (int j = 0; j < 4; j++) {
            int row = m0 + warp_m + i * 16 + row_g;
            int col = n0 + warp_n + j * 8 + col_g;
            float b0 = bias[col], b1 = bias[col + 1];
            float sc = (col < qcols) ? qsc : 1.0f;
            float v00 = (acc[i][j][0] + b0) * sc, v01 = (acc[i][j][1] + b1) * sc;
            float v10 = (acc[i][j][2] + b0) * sc, v11 = (acc[i][j][3] + b1) * sc;
            if (BF16OUT) {
                __nv_bfloat162 h0 = __floats2bfloat162_rn(v00, v01);
                __nv_bfloat162 h1 = __floats2bfloat162_rn(v10, v11);
                __nv_bfloat162 l0 = __floats2bfloat162_rn(
                    v00 - __bfloat162float(h0.x), v01 - __bfloat162float(h0.y));
                __nv_bfloat162 l1 = __floats2bfloat162_rn(
                    v10 - __bfloat162float(h1.x), v11 - __bfloat162float(h1.y));
                *(__nv_bfloat162*)(Ch + (size_t)row * N + col) = h0;
                *(__nv_bfloat162*)(Ch + (size_t)(row + 8) * N + col) = h1;
                *(__nv_bfloat162*)(Cl + (size_t)row * N + col) = l0;
                *(__nv_bfloat162*)(Cl + (size_t)(row + 8) * N + col) = l1;
            } else {
                *(float2*)(C + (size_t)row * N + col) = make_float2(v00, v01);
                *(float2*)(C + (size_t)(row + 8) * N + col) = make_float2(v10, v11);
            }
        }
    }
}

// ---------------------------------------------------------------------------
// Tensor-core flash attention (unchanged R14): 64 q-rows, 128 threads,
// bf16x3 split, ex2 softmax (scale folded into Q), hi/lo output.
// ---------------------------------------------------------------------------
#define APITCH 72
#define ATILE (64 * APITCH)
#define ATT_SMEM ((2 + 8) * ATILE * 2)      // 92160 B

__global__ void __launch_bounds__(128) attn_tc(
    const __nv_bfloat16* __restrict__ qh, const __nv_bfloat16* __restrict__ ql,
    __nv_bfloat16* __restrict__ atth, __nv_bfloat16* __restrict__ attl)
{
    extern __shared__ __nv_bfloat16 sm[];
    __nv_bfloat16* Qh = sm;
    __nv_bfloat16* Ql = Qh + ATILE;
    __nv_bfloat16* KV = Ql + ATILE;

    const int tid = threadIdx.x;
    const int wid = tid >> 5;
    const int lane = tid & 31;
    const int bh = blockIdx.y;
    const int b = bh >> 4, h = bh & 15;
    const int q0 = blockIdx.x * 64;
    const size_t tokbase = (size_t)b * SEQ;

    const uint32_t sQh = smem_u32(Qh), sQl = smem_u32(Ql);
    const uint32_t sKV = smem_u32(KV);

    {
        const size_t qoff = (tokbase + q0) * N_QKV + h * HDIM;
#pragma unroll
        for (int t = 0; t < 4; t++) {
            int idx = tid + t * 128;
            int row = idx >> 3;
            int ch = (idx & 7) * 8;
            *(uint4*)(Qh + row * APITCH + ch) = *(const uint4*)(qh + qoff + (size_t)row * N_QKV + ch);
            *(uint4*)(Ql + row * APITCH + ch) = *(const uint4*)(ql + qoff + (size_t)row * N_QKV + ch);
        }
    }

    auto load_kv = [&](int kt, int p) {
        const size_t koff = (tokbase + kt * 64) * N_QKV + HID + h * HDIM;
        const size_t voff = koff + HID;
        const uint32_t base = sKV + (uint32_t)p * (4 * ATILE * 2);
#pragma unroll
        for (int t = 0; t < 4; t++) {
            int idx = tid + t * 128;
            int row = idx >> 3;
            int ch = (idx & 7) * 8;
            size_t g = (size_t)row * N_QKV + ch;
            uint32_t doff = (uint32_t)((row * APITCH + ch) * 2);
            cp16(base + doff,                 qh + koff + g);
            cp16(base + ATILE * 2 + doff,     ql + koff + g);
            cp16(base + 2 * ATILE * 2 + doff, qh + voff + g);
            cp16(base + 3 * ATILE * 2 + doff, ql + voff + g);
        }
    };

    load_kv(0, 0);
    cp_commit();
    __syncthreads();

    const int lrow = lane & 15;
    const int lkh = (lane >> 4) * 8;
    const int vkey = (lane >> 4) * 8 + (lane & 7);
    const int vd = ((lane >> 3) & 1) * 8;

    uint32_t qfh[4][4], qfl[4][4];
#pragma unroll
    for (int kk = 0; kk < 4; kk++) {
        const uint32_t qoff2 = (uint32_t)(((wid * 16 + lrow) * APITCH + kk * 16 + lkh) * 2);
        ldm_x4(sQh + qoff2, qfh[kk][0], qfh[kk][1], qfh[kk][2], qfh[kk][3]);
        ldm_x4(sQl + qoff2, qfl[kk][0], qfl[kk][1], qfl[kk][2], qfl[kk][3]);
    }

    float l0 = 0.f, l1 = 0.f;
    float o[8][4];
#pragma unroll
    for (int t = 0; t < 8; t++)
#pragma unroll
        for (int q = 0; q < 4; q++) o[t][q] = 0.f;

    const int NK = SEQ / 64;
    for (int kt = 0; kt < NK; kt++) {
        const int p = kt & 1;
        cp_wait<0>();
        __syncthreads();
        if (kt + 1 < NK) load_kv(kt + 1, p ^ 1);
        cp_commit();

        const uint32_t base = sKV + (uint32_t)p * (4 * ATILE * 2);
        const uint32_t sKh = base;
        const uint32_t sKl = base + ATILE * 2;
        const uint32_t sVh = base + 2 * ATILE * 2;
        const uint32_t sVl = base + 3 * ATILE * 2;

        auto load_kfrags = [&](int kk, uint32_t (&kh)[4][4], uint32_t (&kl)[4][4]) {
#pragma unroll
            for (int jp = 0; jp < 4; jp++) {
                const uint32_t koff2 = (uint32_t)(((jp * 16 + lrow) * APITCH + kk * 16 + lkh) * 2);
                ldm_x4(sKh + koff2, kh[jp][0], kh[jp][1], kh[jp][2], kh[jp][3]);
                ldm_x4(sKl + koff2, kl[jp][0], kl[jp][1], kl[jp][2], kl[jp][3]);
            }
        };
        auto load_vfrags = [&](int kk, uint32_t (&vh)[4][4], uint32_t (&vl)[4][4]) {
#pragma unroll
            for (int dt = 0; dt < 4; dt++) {
                const uint32_t voff2 = (uint32_t)(((kk * 16 + vkey) * APITCH + dt * 16 + vd) * 2);
                ldm_x4_t(sVh + voff2, vh[dt][0], vh[dt][1], vh[dt][2], vh[dt][3]);
                ldm_x4_t(sVl + voff2, vl[dt][0], vl[dt][1], vl[dt][2], vl[dt][3]);
            }
        };

        float sf[8][4];
#pragma unroll
        for (int t = 0; t < 8; t++)
#pragma unroll
            for (int q = 0; q < 4; q++) sf[t][q] = 0.f;

        auto s_mma = [&](int kk, uint32_t (&kh)[4][4], uint32_t (&kl)[4][4]) {
#pragma unroll
            for (int jp = 0; jp < 4; jp++) {
                mma_bf16(sf[2 * jp],     qfh[kk], kh[jp][0], kh[jp][2]);
                mma_bf16(sf[2 * jp + 1], qfh[kk], kh[jp][1], kh[jp][3]);
            }
#pragma unroll
            for (int jp = 0; jp < 4; jp++) {
                mma_bf16(sf[2 * jp],     qfh[kk], kl[jp][0], kl[jp][2]);
                mma_bf16(sf[2 * jp + 1], qfh[kk], kl[jp][1], kl[jp][3]);
            }
#pragma unroll
            for (int jp = 0; jp < 4; jp++) {
                mma_bf16(sf[2 * jp],     qfl[kk], kh[jp][0], kh[jp][2]);
                mma_bf16(sf[2 * jp + 1], qfl[kk], kh[jp][1], kh[jp][3]);
            }
        };

        {
            uint32_t khA[4][4], klA[4][4], khB[4][4], klB[4][4];
            load_kfrags(0, khA, klA);
            load_kfrags(1, khB, klB); s_mma(0, khA, klA);
            load_kfrags(2, khA, klA); s_mma(1, khB, klB);
            load_kfrags(3, khB, klB); s_mma(2, khA, klA);
            s_mma(3, khB, klB);
        }

        uint32_t vhA[4][4], vlA[4][4], vhB[4][4], vlB[4][4];
        load_vfrags(0, vhA, vlA);

#pragma unroll
        for (int t = 0; t < 8; t++) {
            sf[t][0] = ex2f(sf[t][0]);
            sf[t][1] = ex2f(sf[t][1]);
            sf[t][2] = ex2f(sf[t][2]);
            sf[t][3] = ex2f(sf[t][3]);
            l0 += sf[t][0] + sf[t][1];
            l1 += sf[t][2] + sf[t][3];
        }

        uint32_t ph[4][4], pl[4][4];
#pragma unroll
        for (int kk = 0; kk < 4; kk++) {
            float* c0 = sf[2 * kk];
            float* c1 = sf[2 * kk + 1];
            ph[kk][0] = packbf(c0[0], c0[1]);
            ph[kk][1] = packbf(c0[2], c0[3]);
            ph[kk][2] = packbf(c1[0], c1[1]);
            ph[kk][3] = packbf(c1[2], c1[3]);
            __nv_bfloat162* hp;
            hp = (__nv_bfloat162*)&ph[kk][0];
            pl[kk][0] = packbf(c0[0] - __bfloat162float(hp->x), c0[1] - __bfloat162float(hp->y));
            hp = (__nv_bfloat162*)&ph[kk][1];
            pl[kk][1] = packbf(c0[2] - __bfloat162float(hp->x), c0[3] - __bfloat162float(hp->y));
            hp = (__nv_bfloat162*)&ph[kk][2];
            pl[kk][2] = packbf(c1[0] - __bfloat162float(hp->x), c1[1] - __bfloat162float(hp->y));
            hp = (__nv_bfloat162*)&ph[kk][3];
            pl[kk][3] = packbf(c1[2] - __bfloat162float(hp->x), c1[3] - __bfloat162float(hp->y));
        }

        auto pv_mma = [&](int kk, uint32_t (&vh)[4][4], uint32_t (&vl)[4][4]) {
#pragma unroll
            for (int dt = 0; dt < 4; dt++) {
                mma_bf16(o[2 * dt],     ph[kk], vh[dt][0], vh[dt][2]);
                mma_bf16(o[2 * dt + 1], ph[kk], vh[dt][1], vh[dt][3]);
            }
#pragma unroll
            for (int dt = 0; dt < 4; dt++) {
                mma_bf16(o[2 * dt],     ph[kk], vl[dt][0], vl[dt][2]);
                mma_bf16(o[2 * dt + 1], ph[kk], vl[dt][1], vl[dt][3]);
            }
#pragma unroll
            for (int dt = 0; dt < 4; dt++) {
                mma_bf16(o[2 * dt],     pl[kk], vh[dt][0], vh[dt][2]);
                mma_bf16(o[2 * dt + 1], pl[kk], vh[dt][1], vh[dt][3]);
            }
        };

        load_vfrags(1, vhB, vlB); pv_mma(0, vhA, vlA);
        load_vfrags(2, vhA, vlA); pv_mma(1, vhB, vlB);
        load_vfrags(3, vhB, vlB); pv_mma(2, vhA, vlA);
        pv_mma(3, vhB, vlB);
    }

    l0 += __shfl_xor_sync(0xffffffffu, l0, 1);
    l0 += __shfl_xor_sync(0xffffffffu, l0, 2);
    l1 += __shfl_xor_sync(0xffffffffu, l1, 1);
    l1 += __shfl_xor_sync(0xffffffffu, l1, 2);

    const float inv0 = 1.f / l0, inv1 = 1.f / l1;
    const int gr0 = q0 + wid * 16 + (lane >> 2);
    const int gr1 = gr0 + 8;
    const size_t r0base = (tokbase + gr0) * (size_t)HID;
    const size_t r1base = (tokbase + gr1) * (size_t)HID;
#pragma unroll
    for (int t = 0; t < 8; t++) {
        int col = h * HDIM + t * 8 + (lane & 3) * 2;
        float v00 = o[t][0] * inv0, v01 = o[t][1] * inv0;
        float v10 = o[t][2] * inv1, v11 = o[t][3] * inv1;
        __nv_bfloat162 h0 = __floats2bfloat162_rn(v00, v01);
        __nv_bfloat162 h1 = __floats2bfloat162_rn(v10, v11);
        __nv_bfloat162 lo0 = __floats2bfloat162_rn(v00 - __bfloat162float(h0.x),
                                                   v01 - __bfloat162float(h0.y));
        __nv_bfloat162 lo1 = __floats2bfloat162_rn(v10 - __bfloat162float(h1.x),
                                                   v11 - __bfloat162float(h1.y));
        *(__nv_bfloat162*)(atth + r0base + col) = h0;
        *(__nv_bfloat162*)(attl + r0base + col) = lo0;
        *(__nv_bfloat162*)(atth + r1base + col) = h1;
        *(__nv_bfloat162*)(attl + r1base + col) = lo1;
    }
}

// ---------------------------------------------------------------------------
// Launch
// ---------------------------------------------------------------------------
extern "C" void kernel_launch(void* const* d_in, const int* in_sizes, int n_in,
                              void* d_out, int out_size)
{
    const float *x = nullptr, *w_qkv = nullptr, *b_qkv = nullptr,
                *w_out = nullptr, *b_out = nullptr;
    for (int i = 0; i < n_in; i++) {
        const float* p = (const float*)d_in[i];
        switch (in_sizes[i]) {
            case M_TOT * HID: x = p; break;
            case N_QKV * HID: w_qkv = p; break;
            case N_QKV:       b_qkv = p; break;
            case HID * HID:   w_out = p; break;
            case HID:         b_out = p; break;
        }
    }
    float* out = (float*)d_out;

    __nv_bfloat16 *qkvh, *qkvl, *xh, *xl, *wqh, *wql, *atth, *attl, *woh, *wol;
    cudaGetSymbolAddress((void**)&qkvh, g_qkvh);
    cudaGetSymbolAddress((void**)&qkvl, g_qkvl);
    cudaGetSymbolAddress((void**)&xh, g_xh);
    cudaGetSymbolAddress((void**)&xl, g_xl);
    cudaGetSymbolAddress((void**)&wqh, g_wqh);
    cudaGetSymbolAddress((void**)&wql, g_wql);
    cudaGetSymbolAddress((void**)&atth, g_atth);
    cudaGetSymbolAddress((void**)&attl, g_attl);
    cudaGetSymbolAddress((void**)&woh, g_woh);
    cudaGetSymbolAddress((void**)&wol, g_wol);

    cudaFuncSetAttribute(attn_tc,
                         cudaFuncAttributeMaxDynamicSharedMemorySize, ATT_SMEM);
    cudaFuncSetAttribute(gemm_hmma<true>,
                         cudaFuncAttributeMaxDynamicSharedMemorySize, GEMM_SMEM);
    cudaFuncSetAttribute(gemm_hmma<false>,
                         cudaFuncAttributeMaxDynamicSharedMemorySize, GEMM_SMEM);

    // Fused split (one launch for x, w_qkv, w_out)
    split_all<<<1184, 256>>>(x, xh, xl, w_qkv, wqh, wql, w_out, woh, wol);

    // GEMM1: qkv = x @ w_qkv^T + b_qkv; Q cols scaled by 0.125*log2e
    gemm_hmma<true><<<dim3(N_QKV / GBN, M_TOT / GBM), dim3(256), GEMM_SMEM>>>(
        xh, xl, wqh, wql, b_qkv, nullptr, qkvh, qkvl, M_TOT, N_QKV, HID,
        QSCALE, HID);

    // Attention
    attn_tc<<<dim3(SEQ / 64, BATCH * NHEAD), dim3(128), ATT_SMEM>>>(
        qkvh, qkvl, atth, attl);

    // GEMM2: out = att @ w_out^T + b_out (no scale)
    gemm_hmma<false><<<dim3(HID / GBN, M_TOT / GBM), dim3(256), GEMM_SMEM>>>(
        atth, attl, woh, wol, b_out, out, nullptr, nullptr, M_TOT, HID, HID,
        1.0f, 0);
}